// round 12
// baseline (speedup 1.0000x reference)
#include <cuda_runtime.h>
#include <math.h>
#include <stdint.h>

// B=4 S=2048 D=1024 H=16 HD=64 F=4096 E=8 K=2, T=8192
#define T_ 8192
#define S_ 2048
#define D_ 1024
#define H_ 16
#define HD_ 64
#define F_ 4096
#define E_ 8
#define BH_ 64

// ---------------- scratch ----------------
__device__ float d_qt[T_ * D_];
__device__ float d_kt[T_ * D_];
__device__ float d_vt[T_ * D_];
__device__ float d_attnx[T_ * D_];      // tf32-rounded at write (feeds ONLY oproj A)
__device__ float d_tmp[T_ * D_];
__device__ float d_x1[T_ * D_];         // RAW fp32 (feeds route + ln2, as in R5)
__device__ float d_x1r[T_ * D_];        // tf32-rounded copy (feeds ONLY moe1 A)
__device__ float d_moe[T_ * D_];
__device__ float d_h[67108864];         // [16384, 4096], tf32-rounded at write (feeds ONLY moe2 A)
__device__ float d_gsc[T_ * E_];
__device__ int   d_tok_e[T_ * 2];
__device__ float d_tok_w[T_ * 2];
__device__ int   d_list[T_ * 2];
__device__ float d_wl[T_ * 2];
__device__ int   d_cnt[E_];
__device__ int   d_fill[E_];
__device__ int   d_base[E_];
// tf32-rounded operand copies
__device__ float d_xt[T_ * D_];
__device__ float d_wq_t[D_ * D_];
__device__ float d_wk_t[D_ * D_];
__device__ float d_wv_t[D_ * D_];
__device__ float d_wo_t[D_ * D_];
__device__ float d_ew1_t[E_ * D_ * F_];
__device__ float d_ew2_t[E_ * F_ * D_];

// ---------------- tf32 mma helpers ----------------
__device__ __forceinline__ unsigned f2tf(float f) {
    unsigned u; asm("cvt.rna.tf32.f32 %0, %1;" : "=r"(u) : "f"(f)); return u;
}
__device__ __forceinline__ float f2tf_f(float f) { return __uint_as_float(f2tf(f)); }
__device__ __forceinline__ void mma8(float* c, const unsigned* a, const unsigned* b) {
    asm volatile("mma.sync.aligned.m16n8k8.row.col.f32.tf32.tf32.f32 "
                 "{%0,%1,%2,%3},{%4,%5,%6,%7},{%8,%9},{%0,%1,%2,%3};"
                 : "+f"(c[0]), "+f"(c[1]), "+f"(c[2]), "+f"(c[3])
                 : "r"(a[0]), "r"(a[1]), "r"(a[2]), "r"(a[3]), "r"(b[0]), "r"(b[1]));
}

__device__ __forceinline__ void cpa16(float* smem, const float* gmem) {
    unsigned s = (unsigned)__cvta_generic_to_shared(smem);
    asm volatile("cp.async.cg.shared.global [%0], [%1], 16;" :: "r"(s), "l"(gmem) : "memory");
}

// ---------------- converts: src -> tf32-rounded dst ----------------
__global__ void k_cvt(const float* __restrict__ src, float* __restrict__ dst, int n4) {
    int i = blockIdx.x * 256 + threadIdx.x;
    if (i < n4) {
        float4 v = ((const float4*)src)[i];
        v.x = f2tf_f(v.x); v.y = f2tf_f(v.y); v.z = f2tf_f(v.z); v.w = f2tf_f(v.w);
        ((float4*)dst)[i] = v;
    }
}

// ---------------- zero ----------------
__global__ void k_zero() {
    int i = blockIdx.x * 256 + threadIdx.x;
    if (i < T_ * D_) d_moe[i] = 0.f;
    if (i < E_) { d_cnt[i] = 0; d_fill[i] = 0; }
}

// ============ async-pipelined NN 128x128 tf32 gemm body ============
// operands already tf32-rounded; raw bits straight into mma.
#define STAGES 3
#define LDA 20
#define LDB_ 136
#define STAGE_F (128 * LDA + 16 * LDB_)
#define GEMM_SMEM (STAGE_F * STAGES * 4)

template <class ARowF, class EpiF>
__device__ __forceinline__ void gemm128_nn(ARowF arow_f, const float* __restrict__ B, int ldb,
                                           int col0, int nk, EpiF epi) {
    extern __shared__ float smem_g[];
    const int tid = threadIdx.x, lane = tid & 31, warp = tid >> 5;
    const int rm = (warp & 1) * 64, cn = (warp >> 1) * 32;
    const int tg = lane & 3, g = lane >> 2;
    float c[4][4][4];
#pragma unroll
    for (int i = 0; i < 4; i++)
#pragma unroll
        for (int j = 0; j < 4; j++)
#pragma unroll
            for (int q = 0; q < 4; q++) c[i][j][q] = 0.f;

    const int ar = tid >> 1, ak = (tid & 1) * 8;
    const int bkr = tid >> 4, bn = (tid & 15) * 8;
    const float* Ap = arow_f(ar);
    const float* Bp = B + (size_t)bkr * ldb + col0 + bn;

    auto issue = [&](int kt) {
        float* As = smem_g + (kt % STAGES) * STAGE_F;
        float* Bs = As + 128 * LDA;
        const float* a = Ap + kt * 16 + ak;
        cpa16(&As[ar * LDA + ak], a);
        cpa16(&As[ar * LDA + ak + 4], a + 4);
        const float* b = Bp + (size_t)(kt * 16) * ldb;
        cpa16(&Bs[bkr * LDB_ + bn], b);
        cpa16(&Bs[bkr * LDB_ + bn + 4], b + 4);
        asm volatile("cp.async.commit_group;" ::: "memory");
    };
    issue(0); issue(1);

    for (int kt = 0; kt < nk; kt++) {
        // Mid-loop: newest committed group is stage kt+1 -> wait_group 1 completes stage kt.
        // Last iteration: newest group IS stage kt -> drain fully.
        if (kt + 1 < nk) { asm volatile("cp.async.wait_group 1;" ::: "memory"); }
        else             { asm volatile("cp.async.wait_group 0;" ::: "memory"); }
        __syncthreads();
        const float* As = smem_g + (kt % STAGES) * STAGE_F;
        const float* Bs = As + 128 * LDA;
#pragma unroll
        for (int ks = 0; ks < 16; ks += 8) {
            unsigned a[4][4], b[4][2];
#pragma unroll
            for (int i = 0; i < 4; i++) {
                a[i][0] = __float_as_uint(As[(rm + i * 16 + g) * LDA + ks + tg]);
                a[i][1] = __float_as_uint(As[(rm + i * 16 + g + 8) * LDA + ks + tg]);
                a[i][2] = __float_as_uint(As[(rm + i * 16 + g) * LDA + ks + tg + 4]);
                a[i][3] = __float_as_uint(As[(rm + i * 16 + g + 8) * LDA + ks + tg + 4]);
            }
#pragma unroll
            for (int j = 0; j < 4; j++) {
                b[j][0] = __float_as_uint(Bs[(ks + tg) * LDB_ + cn + j * 8 + g]);
                b[j][1] = __float_as_uint(Bs[(ks + tg + 4) * LDB_ + cn + j * 8 + g]);
            }
#pragma unroll
            for (int i = 0; i < 4; i++)
#pragma unroll
                for (int j = 0; j < 4; j++) mma8(c[i][j], a[i], b[j]);
        }
        __syncthreads();
        if (kt + 2 < nk) issue(kt + 2);
    }
#pragma unroll
    for (int i = 0; i < 4; i++) {
        int r0 = rm + i * 16 + g;
#pragma unroll
        for (int j = 0; j < 4; j++) {
            int c0 = cn + j * 8 + tg * 2;
            epi(r0, c0, c[i][j][0]); epi(r0, c0 + 1, c[i][j][1]);
            epi(r0 + 8, c0, c[i][j][2]); epi(r0 + 8, c0 + 1, c[i][j][3]);
        }
    }
}

// ---------------- QKV projection ----------------
__global__ __launch_bounds__(256) void k_qkv(
    const float* __restrict__ bq, const float* __restrict__ bk, const float* __restrict__ bv)
{
    const int which = blockIdx.z;
    const float* __restrict__ W    = which == 0 ? d_wq_t : (which == 1 ? d_wk_t : d_wv_t);
    const float* __restrict__ bias = which == 0 ? bq : (which == 1 ? bk : bv);
    float* dst = which == 0 ? d_qt : (which == 1 ? d_kt : d_vt);
    const int row0 = blockIdx.y * 128, col0 = blockIdx.x * 128;
    gemm128_nn([&](int r) { return d_xt + (size_t)(row0 + r) * D_; }, W, D_, col0, D_ / 16,
        [&](int r, int cc, float v) {
            int t = row0 + r, cg = col0 + cc;
            int bi = t >> 11, s = t & 2047, h = cg >> 6, hd = cg & 63;
            dst[(((size_t)(bi * H_ + h)) * S_ + s) * HD_ + hd] = v + bias[cg];
        });
}

// ---------------- O projection ----------------
__global__ __launch_bounds__(256) void k_oproj(const float* __restrict__ bias) {
    const int row0 = blockIdx.y * 128, col0 = blockIdx.x * 128;
    gemm128_nn([&](int r) { return d_attnx + (size_t)(row0 + r) * D_; }, d_wo_t, D_, col0, D_ / 16,
        [&](int r, int cc, float v) {
            d_tmp[(size_t)(row0 + r) * D_ + col0 + cc] = v + bias[col0 + cc];
        });
}

// ---------------- MoE GEMM1 (gather + gelu, tf32-rounded output) ----------------
__global__ __launch_bounds__(256) void k_moe1(const float* __restrict__ eb1) {
    const int e = blockIdx.z;
    const int cnt = d_cnt[e], base = d_base[e];
    const int row0 = blockIdx.y * 128;
    if (row0 >= cnt) return;
    const int col0 = blockIdx.x * 128;
    const float* __restrict__ W = d_ew1_t + (size_t)e * D_ * F_;
    gemm128_nn([&](int r) {
            int rr = row0 + r;
            int token = d_list[base + (rr < cnt ? rr : 0)];
            return d_x1r + (size_t)token * D_;
        }, W, F_, col0, D_ / 16,
        [&](int r, int cc, float v) {
            int rr = row0 + r;
            if (rr < cnt) {
                float t = v + eb1[e * F_ + col0 + cc];
                d_h[(size_t)(base + rr) * F_ + col0 + cc] =
                    f2tf_f(0.5f * t * (1.f + erff(t * 0.70710678118654752f)));
            }
        });
}

// ---------------- MoE GEMM2 (weighted scatter-add) ----------------
__global__ __launch_bounds__(256) void k_moe2(const float* __restrict__ eb2) {
    const int e = blockIdx.z;
    const int cnt = d_cnt[e], base = d_base[e];
    const int row0 = blockIdx.y * 128;
    if (row0 >= cnt) return;
    const int col0 = blockIdx.x * 128;
    const float* __restrict__ W = d_ew2_t + (size_t)e * F_ * D_;
    gemm128_nn([&](int r) {
            int rr = row0 + r;
            return d_h + (size_t)(base + (rr < cnt ? rr : 0)) * F_;
        }, W, D_, col0, F_ / 16,
        [&](int r, int cc, float v) {
            int rr = row0 + r;
            if (rr < cnt) {
                int token = d_list[base + rr];
                float w = d_wl[base + rr];
                atomicAdd(&d_moe[(size_t)token * D_ + col0 + cc],
                          w * (v + eb2[e * D_ + col0 + cc]));
            }
        });
}

// ================= FLASH ATTENTION =================
#define LDK 136
#define LDV 72
__global__ __launch_bounds__(256) void k_flash() {
    extern __shared__ unsigned sm_[];
    unsigned* Ks = sm_;                  // [64][LDK]
    unsigned* Vs = sm_ + 64 * LDK;       // [128][LDV]
    const int bh = blockIdx.y, row0 = blockIdx.x * 128;
    const int tid = threadIdx.x, lane = tid & 31, warp = tid >> 5;
    const int tg = lane & 3, g = lane >> 2;

    const float* Kb = d_kt + (size_t)bh * S_ * HD_;
    const float* Vb = d_vt + (size_t)bh * S_ * HD_;

    unsigned qa[8][4];
    {
        const float* q0 = d_qt + (size_t)(bh * S_ + row0 + warp * 16 + g) * HD_;
        const float* q1 = q0 + 8 * HD_;
#pragma unroll
        for (int kd = 0; kd < 8; kd++) {
            qa[kd][0] = f2tf(0.125f * __ldg(q0 + kd * 8 + tg));
            qa[kd][1] = f2tf(0.125f * __ldg(q1 + kd * 8 + tg));
            qa[kd][2] = f2tf(0.125f * __ldg(q0 + kd * 8 + tg + 4));
            qa[kd][3] = f2tf(0.125f * __ldg(q1 + kd * 8 + tg + 4));
        }
    }

    float o[8][4];
#pragma unroll
    for (int j = 0; j < 8; j++) { o[j][0] = o[j][1] = o[j][2] = o[j][3] = 0.f; }
    float mA = -1e30f, mB = -1e30f, lA = 0.f, lB = 0.f;

    const int fc = tid >> 1;
    const int fh = (tid & 1) * 32;

    for (int kb = 0; kb < S_ / 128; kb++) {
        const float* kp = Kb + (size_t)(kb * 128 + fc) * HD_ + fh;
        const float* vp = Vb + (size_t)(kb * 128 + fc) * HD_ + fh;
#pragma unroll
        for (int i = 0; i < 8; i++) {
            float4 kv = *(const float4*)(kp + 4 * i);
            Ks[(fh + 4 * i + 0) * LDK + fc] = f2tf(kv.x);
            Ks[(fh + 4 * i + 1) * LDK + fc] = f2tf(kv.y);
            Ks[(fh + 4 * i + 2) * LDK + fc] = f2tf(kv.z);
            Ks[(fh + 4 * i + 3) * LDK + fc] = f2tf(kv.w);
            float4 vv = *(const float4*)(vp + 4 * i);
            Vs[fc * LDV + fh + 4 * i + 0] = f2tf(vv.x);
            Vs[fc * LDV + fh + 4 * i + 1] = f2tf(vv.y);
            Vs[fc * LDV + fh + 4 * i + 2] = f2tf(vv.z);
            Vs[fc * LDV + fh + 4 * i + 3] = f2tf(vv.w);
        }
        __syncthreads();

        float c[16][4];
#pragma unroll
        for (int j = 0; j < 16; j++) { c[j][0] = c[j][1] = c[j][2] = c[j][3] = 0.f; }
#pragma unroll
        for (int kd = 0; kd < 8; kd++) {
#pragma unroll
            for (int j = 0; j < 16; j++) {
                unsigned b[2] = { Ks[(kd * 8 + tg) * LDK + j * 8 + g],
                                  Ks[(kd * 8 + tg + 4) * LDK + j * 8 + g] };
                mma8(c[j], qa[kd], b);
            }
        }

        float rmA = -1e30f, rmB = -1e30f;
#pragma unroll
        for (int j = 0; j < 16; j++) {
            rmA = fmaxf(rmA, fmaxf(c[j][0], c[j][1]));
            rmB = fmaxf(rmB, fmaxf(c[j][2], c[j][3]));
        }
        rmA = fmaxf(rmA, __shfl_xor_sync(~0u, rmA, 1));
        rmA = fmaxf(rmA, __shfl_xor_sync(~0u, rmA, 2));
        rmB = fmaxf(rmB, __shfl_xor_sync(~0u, rmB, 1));
        rmB = fmaxf(rmB, __shfl_xor_sync(~0u, rmB, 2));
        float nmA = fmaxf(mA, rmA), nmB = fmaxf(mB, rmB);
        float aA = __expf(mA - nmA), aB = __expf(mB - nmB);
        float sA = 0.f, sB = 0.f;
#pragma unroll
        for (int j = 0; j < 16; j++) {
            c[j][0] = __expf(c[j][0] - nmA); c[j][1] = __expf(c[j][1] - nmA);
            c[j][2] = __expf(c[j][2] - nmB); c[j][3] = __expf(c[j][3] - nmB);
            sA += c[j][0] + c[j][1]; sB += c[j][2] + c[j][3];
        }
        sA += __shfl_xor_sync(~0u, sA, 1); sA += __shfl_xor_sync(~0u, sA, 2);
        sB += __shfl_xor_sync(~0u, sB, 1); sB += __shfl_xor_sync(~0u, sB, 2);
        lA = lA * aA + sA; lB = lB * aB + sB;
        mA = nmA; mB = nmB;
#pragma unroll
        for (int j = 0; j < 8; j++) {
            o[j][0] *= aA; o[j][1] *= aA; o[j][2] *= aB; o[j][3] *= aB;
        }

        const int srcA = (lane & 28) | (tg >> 1);
        const bool hi = tg & 1;
#pragma unroll
        for (int t = 0; t < 16; t++) {
            float v00 = __shfl_sync(~0u, c[t][0], srcA);
            float v01 = __shfl_sync(~0u, c[t][1], srcA);
            float v02 = __shfl_sync(~0u, c[t][2], srcA);
            float v03 = __shfl_sync(~0u, c[t][3], srcA);
            float v10 = __shfl_sync(~0u, c[t][0], srcA + 2);
            float v11 = __shfl_sync(~0u, c[t][1], srcA + 2);
            float v12 = __shfl_sync(~0u, c[t][2], srcA + 2);
            float v13 = __shfl_sync(~0u, c[t][3], srcA + 2);
            unsigned a[4] = { f2tf(hi ? v01 : v00), f2tf(hi ? v03 : v02),
                              f2tf(hi ? v11 : v10), f2tf(hi ? v13 : v12) };
#pragma unroll
            for (int jo = 0; jo < 8; jo++) {
                unsigned b[2] = { Vs[(t * 8 + tg) * LDV + jo * 8 + g],
                                  Vs[(t * 8 + tg + 4) * LDV + jo * 8 + g] };
                mma8(o[jo], a, b);
            }
        }
        __syncthreads();
    }

    // epilogue: divide by l, tf32-round (feeds only oproj A), store
    const float iA = 1.f / lA, iB = 1.f / lB;
    const int b_ = bh >> 4, h = bh & 15;
    const int rA = row0 + warp * 16 + g;
    float* oA = d_attnx + ((size_t)(b_ * S_ + rA)) * D_ + h * HD_;
    float* oB = oA + 8 * D_;
#pragma unroll
    for (int jo = 0; jo < 8; jo++) {
        *(float2*)(oA + jo * 8 + tg * 2) = make_float2(f2tf_f(o[jo][0] * iA), f2tf_f(o[jo][1] * iA));
        *(float2*)(oB + jo * 8 + tg * 2) = make_float2(f2tf_f(o[jo][2] * iB), f2tf_f(o[jo][3] * iB));
    }
}

// ---------------- layernorm ----------------
// ln1: writes RAW result to out (route/ln2 consumers, matches R5 exactly)
//      and tf32-rounded copy to out_r (moe1 A operand). ln2: out only.
template <bool DUAL>
__device__ __forceinline__ void ln_body(const float* __restrict__ a, const float* __restrict__ add,
                                        const float* __restrict__ g, const float* __restrict__ be,
                                        float* __restrict__ out, float* __restrict__ out_r) {
    const int t = blockIdx.x, tid = threadIdx.x;
    __shared__ float v[D_];
    __shared__ float red[256];
    float s = 0.f;
    for (int j = tid; j < D_; j += 256) {
        float xv = a[(size_t)t * D_ + j] + add[(size_t)t * D_ + j];
        v[j] = xv; s += xv;
    }
    red[tid] = s; __syncthreads();
    for (int o = 128; o > 0; o >>= 1) { if (tid < o) red[tid] += red[tid + o]; __syncthreads(); }
    float mu = red[0] * (1.f / D_); __syncthreads();
    float s2 = 0.f;
    for (int j = tid; j < D_; j += 256) { float d = v[j] - mu; s2 += d * d; }
    red[tid] = s2; __syncthreads();
    for (int o = 128; o > 0; o >>= 1) { if (tid < o) red[tid] += red[tid + o]; __syncthreads(); }
    float rstd = rsqrtf(red[0] * (1.f / D_) + 1e-5f);
    for (int j = tid; j < D_; j += 256) {
        float r = (v[j] - mu) * rstd * g[j] + be[j];
        out[(size_t)t * D_ + j] = r;
        if (DUAL) out_r[(size_t)t * D_ + j] = f2tf_f(r);
    }
}
__global__ __launch_bounds__(256) void k_ln1(const float* __restrict__ x,
                                             const float* __restrict__ g, const float* __restrict__ be) {
    ln_body<true>(x, d_tmp, g, be, d_x1, d_x1r);
}
__global__ __launch_bounds__(256) void k_ln2(const float* __restrict__ g, const float* __restrict__ be,
                                             float* __restrict__ out) {
    ln_body<false>(d_x1, d_moe, g, be, out, nullptr);
}

// ---------------- routing (reads RAW d_x1, identical to R5) ----------------
__global__ __launch_bounds__(128) void k_route(const float* __restrict__ gW, const float* __restrict__ gb) {
    const int t = blockIdx.x, tid = threadIdx.x;
    float p[E_];
#pragma unroll
    for (int e = 0; e < E_; e++) p[e] = 0.f;
    for (int d = tid; d < D_; d += 128) {
        float xv = d_x1[(size_t)t * D_ + d];
        const float* w = gW + (size_t)d * E_;
#pragma unroll
        for (int e = 0; e < E_; e++) p[e] += xv * w[e];
    }
    __shared__ float red[128][E_];
#pragma unroll
    for (int e = 0; e < E_; e++) red[tid][e] = p[e];
    __syncthreads();
    for (int o = 64; o > 0; o >>= 1) {
        if (tid < o) {
#pragma unroll
            for (int e = 0; e < E_; e++) red[tid][e] += red[tid + o][e];
        }
        __syncthreads();
    }
    if (tid == 0) {
        float l[E_], m = -1e30f;
#pragma unroll
        for (int e = 0; e < E_; e++) { l[e] = red[0][e] + gb[e]; m = fmaxf(m, l[e]); }
        float s = 0.f;
#pragma unroll
        for (int e = 0; e < E_; e++) { l[e] = expf(l[e] - m); s += l[e]; }
        float inv = 1.f / s;
#pragma unroll
        for (int e = 0; e < E_; e++) { l[e] *= inv; d_gsc[t * E_ + e] = l[e]; }
        int i1 = 0;
#pragma unroll
        for (int e = 1; e < E_; e++) if (l[e] > l[i1]) i1 = e;
        int i2 = -1;
#pragma unroll
        for (int e = 0; e < E_; e++) if (e != i1 && (i2 < 0 || l[e] > l[i2])) i2 = e;
        float tot = l[i1] + l[i2];
        d_tok_e[t * 2 + 0] = i1; d_tok_e[t * 2 + 1] = i2;
        d_tok_w[t * 2 + 0] = l[i1] / tot; d_tok_w[t * 2 + 1] = l[i2] / tot;
        atomicAdd(&d_cnt[i1], 1); atomicAdd(&d_cnt[i2], 1);
    }
}

__global__ __launch_bounds__(256) void k_aux(float* __restrict__ aux_out) {
    __shared__ double red[256];
    __shared__ double rw[E_];
    const int tid = threadIdx.x;
    for (int e = 0; e < E_; e++) {
        double s = 0.0;
        for (int t = tid; t < T_; t += 256) s += (double)d_gsc[t * E_ + e];
        red[tid] = s; __syncthreads();
        for (int o = 128; o > 0; o >>= 1) { if (tid < o) red[tid] += red[tid + o]; __syncthreads(); }
        if (tid == 0) rw[e] = red[0] / (double)T_;
        __syncthreads();
    }
    if (tid == 0) {
        double aux = 0.0; int b = 0;
        for (int e = 0; e < E_; e++) {
            aux += ((double)d_cnt[e] / (double)(T_ * 2)) * rw[e];
            d_base[e] = b; b += d_cnt[e];
        }
        *aux_out = (float)((double)E_ * aux);
    }
}

__global__ void k_fill() {
    const int t = blockIdx.x * 256 + threadIdx.x;
    if (t >= T_) return;
    for (int k = 0; k < 2; k++) {
        int e = d_tok_e[t * 2 + k];
        int slot = atomicAdd(&d_fill[e], 1);
        d_list[d_base[e] + slot] = t;
        d_wl[d_base[e] + slot] = d_tok_w[t * 2 + k];
    }
}

// ---------------- launch ----------------
extern "C" void kernel_launch(void* const* d_in, const int* in_sizes, int n_in,
                              void* d_out, int out_size) {
    const float* x     = (const float*)d_in[0];
    const float* Wq    = (const float*)d_in[1];
    const float* bq    = (const float*)d_in[2];
    const float* Wk    = (const float*)d_in[3];
    const float* bk    = (const float*)d_in[4];
    const float* Wv    = (const float*)d_in[5];
    const float* bv    = (const float*)d_in[6];
    const float* Wo    = (const float*)d_in[7];
    const float* bo    = (const float*)d_in[8];
    const float* g1    = (const float*)d_in[9];
    const float* beta1 = (const float*)d_in[10];
    const float* gateW = (const float*)d_in[11];
    const float* gateb = (const float*)d_in[12];
    const float* eW1   = (const float*)d_in[13];
    const float* eb1   = (const float*)d_in[14];
    const float* eW2   = (const float*)d_in[15];
    const float* eb2   = (const float*)d_in[16];
    const float* g2    = (const float*)d_in[17];
    const float* beta2 = (const float*)d_in[18];
    float* out = (float*)d_out;

    const int flash_smem = (64 * LDK + 128 * LDV) * 4;  // 71680 B
    static int attr_set = 0;
    if (!attr_set) {
        cudaFuncSetAttribute(k_flash, cudaFuncAttributeMaxDynamicSharedMemorySize, flash_smem);
        cudaFuncSetAttribute(k_qkv,   cudaFuncAttributeMaxDynamicSharedMemorySize, GEMM_SMEM);
        cudaFuncSetAttribute(k_oproj, cudaFuncAttributeMaxDynamicSharedMemorySize, GEMM_SMEM);
        cudaFuncSetAttribute(k_moe1,  cudaFuncAttributeMaxDynamicSharedMemorySize, GEMM_SMEM);
        cudaFuncSetAttribute(k_moe2,  cudaFuncAttributeMaxDynamicSharedMemorySize, GEMM_SMEM);
        attr_set = 1;
    }

    // device-global addresses for convert targets
    float *wq_t, *wk_t, *wv_t, *wo_t, *ew1_t, *ew2_t, *xt;
    cudaGetSymbolAddress((void**)&wq_t, d_wq_t);
    cudaGetSymbolAddress((void**)&wk_t, d_wk_t);
    cudaGetSymbolAddress((void**)&wv_t, d_wv_t);
    cudaGetSymbolAddress((void**)&wo_t, d_wo_t);
    cudaGetSymbolAddress((void**)&ew1_t, d_ew1_t);
    cudaGetSymbolAddress((void**)&ew2_t, d_ew2_t);
    cudaGetSymbolAddress((void**)&xt, d_xt);

    const int n4_dd = D_ * D_ / 4, n4_e = E_ * D_ * F_ / 4, n4_x = T_ * D_ / 4;
    k_cvt<<<(n4_dd + 255) / 256, 256>>>(Wq, wq_t, n4_dd);
    k_cvt<<<(n4_dd + 255) / 256, 256>>>(Wk, wk_t, n4_dd);
    k_cvt<<<(n4_dd + 255) / 256, 256>>>(Wv, wv_t, n4_dd);
    k_cvt<<<(n4_dd + 255) / 256, 256>>>(Wo, wo_t, n4_dd);
    k_cvt<<<(n4_e + 255) / 256, 256>>>(eW1, ew1_t, n4_e);
    k_cvt<<<(n4_e + 255) / 256, 256>>>(eW2, ew2_t, n4_e);
    k_cvt<<<(n4_x + 255) / 256, 256>>>(x, xt, n4_x);

    k_zero<<<(T_ * D_) / 256, 256>>>();
    k_qkv<<<dim3(D_ / 128, T_ / 128, 3), 256, GEMM_SMEM>>>(bq, bk, bv);
    k_flash<<<dim3(S_ / 128, BH_), 256, flash_smem>>>();
    k_oproj<<<dim3(D_ / 128, T_ / 128), 256, GEMM_SMEM>>>(bo);
    k_ln1<<<T_, 256>>>(x, g1, beta1);
    k_route<<<T_, 128>>>(gateW, gateb);
    k_aux<<<1, 256>>>(out + (out_size - 1));
    k_fill<<<T_ / 256, 256>>>();
    k_moe1<<<dim3(F_ / 128, T_ / 128, E_), 256, GEMM_SMEM>>>(eb1);
    k_moe2<<<dim3(D_ / 128, T_ / 128, E_), 256, GEMM_SMEM>>>(eb2);
    k_ln2<<<T_, 256>>>(g2, beta2, out);
}

// round 15
// speedup vs baseline: 1.0038x; 1.0038x over previous
#include <cuda_runtime.h>
#include <math.h>
#include <stdint.h>

// B=4 S=2048 D=1024 H=16 HD=64 F=4096 E=8 K=2, T=8192
#define T_ 8192
#define S_ 2048
#define D_ 1024
#define H_ 16
#define HD_ 64
#define F_ 4096
#define E_ 8
#define BH_ 64

// ---------------- scratch ----------------
__device__ float d_qt[T_ * D_];
__device__ float d_kt[T_ * D_];
__device__ float d_vt[T_ * D_];
__device__ float d_attnx[T_ * D_];      // tf32-rounded at write (feeds ONLY oproj A)
__device__ float d_tmp[T_ * D_];
__device__ float d_x1[T_ * D_];         // RAW fp32 (feeds route + ln2)
__device__ float d_x1r[T_ * D_];        // tf32-rounded copy (feeds ONLY moe1 A)
__device__ float d_moe[T_ * D_];
__device__ float d_h[67108864];         // [16384, 4096], tf32-rounded at write
__device__ float d_gsc[T_ * E_];
__device__ int   d_tok_e[T_ * 2];
__device__ float d_tok_w[T_ * 2];
__device__ int   d_list[T_ * 2];
__device__ float d_wl[T_ * 2];
__device__ int   d_cnt[E_];
__device__ int   d_fill[E_];
__device__ int   d_base[E_];
// tf32-rounded operand copies
__device__ float d_xt[T_ * D_];
__device__ float d_wq_t[D_ * D_];
__device__ float d_wk_t[D_ * D_];
__device__ float d_wv_t[D_ * D_];
__device__ float d_wo_t[D_ * D_];
__device__ float d_ew1_t[E_ * D_ * F_];
__device__ float d_ew2_t[E_ * F_ * D_];

// ---------------- tf32 mma helpers ----------------
__device__ __forceinline__ unsigned f2tf(float f) {
    unsigned u; asm("cvt.rna.tf32.f32 %0, %1;" : "=r"(u) : "f"(f)); return u;
}
__device__ __forceinline__ float f2tf_f(float f) { return __uint_as_float(f2tf(f)); }
__device__ __forceinline__ void mma8(float* c, const unsigned* a, const unsigned* b) {
    asm volatile("mma.sync.aligned.m16n8k8.row.col.f32.tf32.tf32.f32 "
                 "{%0,%1,%2,%3},{%4,%5,%6,%7},{%8,%9},{%0,%1,%2,%3};"
                 : "+f"(c[0]), "+f"(c[1]), "+f"(c[2]), "+f"(c[3])
                 : "r"(a[0]), "r"(a[1]), "r"(a[2]), "r"(a[3]), "r"(b[0]), "r"(b[1]));
}

__device__ __forceinline__ void cpa16(float* smem, const float* gmem) {
    unsigned s = (unsigned)__cvta_generic_to_shared(smem);
    asm volatile("cp.async.cg.shared.global [%0], [%1], 16;" :: "r"(s), "l"(gmem) : "memory");
}

// ---------------- converts: src -> tf32-rounded dst ----------------
__global__ void k_cvt(const float* __restrict__ src, float* __restrict__ dst, int n4) {
    int i = blockIdx.x * 256 + threadIdx.x;
    if (i < n4) {
        float4 v = ((const float4*)src)[i];
        v.x = f2tf_f(v.x); v.y = f2tf_f(v.y); v.z = f2tf_f(v.z); v.w = f2tf_f(v.w);
        ((float4*)dst)[i] = v;
    }
}

// ---------------- zero ----------------
__global__ void k_zero() {
    int i = blockIdx.x * 256 + threadIdx.x;
    if (i < T_ * D_) d_moe[i] = 0.f;
    if (i < E_) { d_cnt[i] = 0; d_fill[i] = 0; }
}

// ============ async-pipelined NN 128x128 tf32 gemm body ============
// K-tile 32, 3 stages, ONE barrier per iteration.
#define KT 32
#define LDA 36
#define LDB_ 136
#define STAGE_F (128 * LDA + KT * LDB_)   // 4608 + 4352 = 8960 floats
#define GEMM_SMEM (STAGE_F * 3 * 4)        // 107520 bytes

template <class ARowF, class EpiF>
__device__ __forceinline__ void gemm128_nn(ARowF arow_f, const float* __restrict__ B, int ldb,
                                           int col0, int nkt, EpiF epi) {
    extern __shared__ float smem_g[];
    const int tid = threadIdx.x, lane = tid & 31, warp = tid >> 5;
    const int rm = (warp & 1) * 64, cn = (warp >> 1) * 32;
    const int tg = lane & 3, g = lane >> 2;
    float c[4][4][4];
#pragma unroll
    for (int i = 0; i < 4; i++)
#pragma unroll
        for (int j = 0; j < 4; j++)
#pragma unroll
            for (int q = 0; q < 4; q++) c[i][j][q] = 0.f;

    // fill mapping: A row = tid>>1, 16 k-values at (tid&1)*16; B rows tid>>4 and +16, 8 cols at (tid&15)*8
    const int ar = tid >> 1, akb = (tid & 1) * 16;
    const int br = tid >> 4, bcol = (tid & 15) * 8;
    const float* Ap = arow_f(ar);
    const float* Bp = B + col0 + bcol;

    auto issue = [&](int kt) {
        float* As = smem_g + (kt % 3) * STAGE_F;
        float* Bs = As + 128 * LDA;
        const float* a = Ap + kt * KT + akb;
        cpa16(&As[ar * LDA + akb + 0],  a + 0);
        cpa16(&As[ar * LDA + akb + 4],  a + 4);
        cpa16(&As[ar * LDA + akb + 8],  a + 8);
        cpa16(&As[ar * LDA + akb + 12], a + 12);
        const float* b0 = Bp + (size_t)(kt * KT + br) * ldb;
        const float* b1 = Bp + (size_t)(kt * KT + br + 16) * ldb;
        cpa16(&Bs[br * LDB_ + bcol],            b0);
        cpa16(&Bs[br * LDB_ + bcol + 4],        b0 + 4);
        cpa16(&Bs[(br + 16) * LDB_ + bcol],     b1);
        cpa16(&Bs[(br + 16) * LDB_ + bcol + 4], b1 + 4);
        asm volatile("cp.async.commit_group;" ::: "memory");
    };
    issue(0); issue(1);

    for (int kt = 0; kt < nkt; kt++) {
        if (kt + 1 < nkt) { asm volatile("cp.async.wait_group 1;" ::: "memory"); }
        else             { asm volatile("cp.async.wait_group 0;" ::: "memory"); }
        __syncthreads();
        // stage (kt+2)%3 == (kt-1)%3: fully consumed (certified by the barrier above)
        if (kt + 2 < nkt) issue(kt + 2);
        const float* As = smem_g + (kt % 3) * STAGE_F;
        const float* Bs = As + 128 * LDA;
#pragma unroll
        for (int ks = 0; ks < KT; ks += 8) {
            unsigned a[4][4], b[4][2];
#pragma unroll
            for (int i = 0; i < 4; i++) {
                a[i][0] = __float_as_uint(As[(rm + i * 16 + g) * LDA + ks + tg]);
                a[i][1] = __float_as_uint(As[(rm + i * 16 + g + 8) * LDA + ks + tg]);
                a[i][2] = __float_as_uint(As[(rm + i * 16 + g) * LDA + ks + tg + 4]);
                a[i][3] = __float_as_uint(As[(rm + i * 16 + g + 8) * LDA + ks + tg + 4]);
            }
#pragma unroll
            for (int j = 0; j < 4; j++) {
                b[j][0] = __float_as_uint(Bs[(ks + tg) * LDB_ + cn + j * 8 + g]);
                b[j][1] = __float_as_uint(Bs[(ks + tg + 4) * LDB_ + cn + j * 8 + g]);
            }
#pragma unroll
            for (int i = 0; i < 4; i++)
#pragma unroll
                for (int j = 0; j < 4; j++) mma8(c[i][j], a[i], b[j]);
        }
    }
#pragma unroll
    for (int i = 0; i < 4; i++) {
        int r0 = rm + i * 16 + g;
#pragma unroll
        for (int j = 0; j < 4; j++) {
            int c0 = cn + j * 8 + tg * 2;
            epi(r0, c0, c[i][j][0]); epi(r0, c0 + 1, c[i][j][1]);
            epi(r0 + 8, c0, c[i][j][2]); epi(r0 + 8, c0 + 1, c[i][j][3]);
        }
    }
}

// ---------------- QKV projection ----------------
__global__ __launch_bounds__(256) void k_qkv(
    const float* __restrict__ bq, const float* __restrict__ bk, const float* __restrict__ bv)
{
    const int which = blockIdx.z;
    const float* __restrict__ W    = which == 0 ? d_wq_t : (which == 1 ? d_wk_t : d_wv_t);
    const float* __restrict__ bias = which == 0 ? bq : (which == 1 ? bk : bv);
    float* dst = which == 0 ? d_qt : (which == 1 ? d_kt : d_vt);
    const int row0 = blockIdx.y * 128, col0 = blockIdx.x * 128;
    gemm128_nn([&](int r) { return d_xt + (size_t)(row0 + r) * D_; }, W, D_, col0, D_ / KT,
        [&](int r, int cc, float v) {
            int t = row0 + r, cg = col0 + cc;
            int bi = t >> 11, s = t & 2047, h = cg >> 6, hd = cg & 63;
            dst[(((size_t)(bi * H_ + h)) * S_ + s) * HD_ + hd] = v + bias[cg];
        });
}

// ---------------- O projection ----------------
__global__ __launch_bounds__(256) void k_oproj(const float* __restrict__ bias) {
    const int row0 = blockIdx.y * 128, col0 = blockIdx.x * 128;
    gemm128_nn([&](int r) { return d_attnx + (size_t)(row0 + r) * D_; }, d_wo_t, D_, col0, D_ / KT,
        [&](int r, int cc, float v) {
            d_tmp[(size_t)(row0 + r) * D_ + col0 + cc] = v + bias[col0 + cc];
        });
}

// ---------------- MoE GEMM1 (gather + gelu, tf32-rounded output) ----------------
__global__ __launch_bounds__(256) void k_moe1(const float* __restrict__ eb1) {
    const int e = blockIdx.z;
    const int cnt = d_cnt[e], base = d_base[e];
    const int row0 = blockIdx.y * 128;
    if (row0 >= cnt) return;
    const int col0 = blockIdx.x * 128;
    const float* __restrict__ W = d_ew1_t + (size_t)e * D_ * F_;
    gemm128_nn([&](int r) {
            int rr = row0 + r;
            int token = d_list[base + (rr < cnt ? rr : 0)];
            return d_x1r + (size_t)token * D_;
        }, W, F_, col0, D_ / KT,
        [&](int r, int cc, float v) {
            int rr = row0 + r;
            if (rr < cnt) {
                float t = v + eb1[e * F_ + col0 + cc];
                d_h[(size_t)(base + rr) * F_ + col0 + cc] =
                    f2tf_f(0.5f * t * (1.f + erff(t * 0.70710678118654752f)));
            }
        });
}

// ---------------- MoE GEMM2 (weighted scatter-add) ----------------
__global__ __launch_bounds__(256) void k_moe2(const float* __restrict__ eb2) {
    const int e = blockIdx.z;
    const int cnt = d_cnt[e], base = d_base[e];
    const int row0 = blockIdx.y * 128;
    if (row0 >= cnt) return;
    const int col0 = blockIdx.x * 128;
    const float* __restrict__ W = d_ew2_t + (size_t)e * F_ * D_;
    gemm128_nn([&](int r) {
            int rr = row0 + r;
            return d_h + (size_t)(base + (rr < cnt ? rr : 0)) * F_;
        }, W, D_, col0, F_ / KT,
        [&](int r, int cc, float v) {
            int rr = row0 + r;
            if (rr < cnt) {
                int token = d_list[base + rr];
                float w = d_wl[base + rr];
                atomicAdd(&d_moe[(size_t)token * D_ + col0 + cc],
                          w * (v + eb2[e * D_ + col0 + cc]));
            }
        });
}

// ================= FLASH ATTENTION =================
#define LDK 136
#define LDV 72
__global__ __launch_bounds__(256) void k_flash() {
    extern __shared__ unsigned sm_[];
    unsigned* Ks = sm_;                  // [64][LDK]
    unsigned* Vs = sm_ + 64 * LDK;       // [128][LDV]
    const int bh = blockIdx.y, row0 = blockIdx.x * 128;
    const int tid = threadIdx.x, lane = tid & 31, warp = tid >> 5;
    const int tg = lane & 3, g = lane >> 2;

    const float* Kb = d_kt + (size_t)bh * S_ * HD_;
    const float* Vb = d_vt + (size_t)bh * S_ * HD_;

    unsigned qa[8][4];
    {
        const float* q0 = d_qt + (size_t)(bh * S_ + row0 + warp * 16 + g) * HD_;
        const float* q1 = q0 + 8 * HD_;
#pragma unroll
        for (int kd = 0; kd < 8; kd++) {
            qa[kd][0] = f2tf(0.125f * __ldg(q0 + kd * 8 + tg));
            qa[kd][1] = f2tf(0.125f * __ldg(q1 + kd * 8 + tg));
            qa[kd][2] = f2tf(0.125f * __ldg(q0 + kd * 8 + tg + 4));
            qa[kd][3] = f2tf(0.125f * __ldg(q1 + kd * 8 + tg + 4));
        }
    }

    float o[8][4];
#pragma unroll
    for (int j = 0; j < 8; j++) { o[j][0] = o[j][1] = o[j][2] = o[j][3] = 0.f; }
    float mA = -1e30f, mB = -1e30f, lA = 0.f, lB = 0.f;

    const int fc = tid >> 1;
    const int fh = (tid & 1) * 32;

    for (int kb = 0; kb < S_ / 128; kb++) {
        const float* kp = Kb + (size_t)(kb * 128 + fc) * HD_ + fh;
        const float* vp = Vb + (size_t)(kb * 128 + fc) * HD_ + fh;
#pragma unroll
        for (int i = 0; i < 8; i++) {
            float4 kv = *(const float4*)(kp + 4 * i);
            Ks[(fh + 4 * i + 0) * LDK + fc] = f2tf(kv.x);
            Ks[(fh + 4 * i + 1) * LDK + fc] = f2tf(kv.y);
            Ks[(fh + 4 * i + 2) * LDK + fc] = f2tf(kv.z);
            Ks[(fh + 4 * i + 3) * LDK + fc] = f2tf(kv.w);
            float4 vv = *(const float4*)(vp + 4 * i);
            Vs[fc * LDV + fh + 4 * i + 0] = f2tf(vv.x);
            Vs[fc * LDV + fh + 4 * i + 1] = f2tf(vv.y);
            Vs[fc * LDV + fh + 4 * i + 2] = f2tf(vv.z);
            Vs[fc * LDV + fh + 4 * i + 3] = f2tf(vv.w);
        }
        __syncthreads();

        float c[16][4];
#pragma unroll
        for (int j = 0; j < 16; j++) { c[j][0] = c[j][1] = c[j][2] = c[j][3] = 0.f; }
#pragma unroll
        for (int kd = 0; kd < 8; kd++) {
#pragma unroll
            for (int j = 0; j < 16; j++) {
                unsigned b[2] = { Ks[(kd * 8 + tg) * LDK + j * 8 + g],
                                  Ks[(kd * 8 + tg + 4) * LDK + j * 8 + g] };
                mma8(c[j], qa[kd], b);
            }
        }

        float rmA = -1e30f, rmB = -1e30f;
#pragma unroll
        for (int j = 0; j < 16; j++) {
            rmA = fmaxf(rmA, fmaxf(c[j][0], c[j][1]));
            rmB = fmaxf(rmB, fmaxf(c[j][2], c[j][3]));
        }
        rmA = fmaxf(rmA, __shfl_xor_sync(~0u, rmA, 1));
        rmA = fmaxf(rmA, __shfl_xor_sync(~0u, rmA, 2));
        rmB = fmaxf(rmB, __shfl_xor_sync(~0u, rmB, 1));
        rmB = fmaxf(rmB, __shfl_xor_sync(~0u, rmB, 2));
        float nmA = fmaxf(mA, rmA), nmB = fmaxf(mB, rmB);
        float aA = __expf(mA - nmA), aB = __expf(mB - nmB);
        float sA = 0.f, sB = 0.f;
#pragma unroll
        for (int j = 0; j < 16; j++) {
            c[j][0] = __expf(c[j][0] - nmA); c[j][1] = __expf(c[j][1] - nmA);
            c[j][2] = __expf(c[j][2] - nmB); c[j][3] = __expf(c[j][3] - nmB);
            sA += c[j][0] + c[j][1]; sB += c[j][2] + c[j][3];
        }
        sA += __shfl_xor_sync(~0u, sA, 1); sA += __shfl_xor_sync(~0u, sA, 2);
        sB += __shfl_xor_sync(~0u, sB, 1); sB += __shfl_xor_sync(~0u, sB, 2);
        lA = lA * aA + sA; lB = lB * aB + sB;
        mA = nmA; mB = nmB;
#pragma unroll
        for (int j = 0; j < 8; j++) {
            o[j][0] *= aA; o[j][1] *= aA; o[j][2] *= aB; o[j][3] *= aB;
        }

        const int srcA = (lane & 28) | (tg >> 1);
        const bool hi = tg & 1;
#pragma unroll
        for (int t = 0; t < 16; t++) {
            float v00 = __shfl_sync(~0u, c[t][0], srcA);
            float v01 = __shfl_sync(~0u, c[t][1], srcA);
            float v02 = __shfl_sync(~0u, c[t][2], srcA);
            float v03 = __shfl_sync(~0u, c[t][3], srcA);
            float v10 = __shfl_sync(~0u, c[t][0], srcA + 2);
            float v11 = __shfl_sync(~0u, c[t][1], srcA + 2);
            float v12 = __shfl_sync(~0u, c[t][2], srcA + 2);
            float v13 = __shfl_sync(~0u, c[t][3], srcA + 2);
            unsigned a[4] = { f2tf(hi ? v01 : v00), f2tf(hi ? v03 : v02),
                              f2tf(hi ? v11 : v10), f2tf(hi ? v13 : v12) };
#pragma unroll
            for (int jo = 0; jo < 8; jo++) {
                unsigned b[2] = { Vs[(t * 8 + tg) * LDV + jo * 8 + g],
                                  Vs[(t * 8 + tg + 4) * LDV + jo * 8 + g] };
                mma8(o[jo], a, b);
            }
        }
        __syncthreads();
    }

    const float iA = 1.f / lA, iB = 1.f / lB;
    const int b_ = bh >> 4, h = bh & 15;
    const int rA = row0 + warp * 16 + g;
    float* oA = d_attnx + ((size_t)(b_ * S_ + rA)) * D_ + h * HD_;
    float* oB = oA + 8 * D_;
#pragma unroll
    for (int jo = 0; jo < 8; jo++) {
        *(float2*)(oA + jo * 8 + tg * 2) = make_float2(f2tf_f(o[jo][0] * iA), f2tf_f(o[jo][1] * iA));
        *(float2*)(oB + jo * 8 + tg * 2) = make_float2(f2tf_f(o[jo][2] * iB), f2tf_f(o[jo][3] * iB));
    }
}

// ---------------- layernorm ----------------
template <bool DUAL>
__device__ __forceinline__ void ln_body(const float* __restrict__ a, const float* __restrict__ add,
                                        const float* __restrict__ g, const float* __restrict__ be,
                                        float* __restrict__ out, float* __restrict__ out_r) {
    const int t = blockIdx.x, tid = threadIdx.x;
    __shared__ float v[D_];
    __shared__ float red[256];
    float s = 0.f;
    for (int j = tid; j < D_; j += 256) {
        float xv = a[(size_t)t * D_ + j] + add[(size_t)t * D_ + j];
        v[j] = xv; s += xv;
    }
    red[tid] = s; __syncthreads();
    for (int o = 128; o > 0; o >>= 1) { if (tid < o) red[tid] += red[tid + o]; __syncthreads(); }
    float mu = red[0] * (1.f / D_); __syncthreads();
    float s2 = 0.f;
    for (int j = tid; j < D_; j += 256) { float d = v[j] - mu; s2 += d * d; }
    red[tid] = s2; __syncthreads();
    for (int o = 128; o > 0; o >>= 1) { if (tid < o) red[tid] += red[tid + o]; __syncthreads(); }
    float rstd = rsqrtf(red[0] * (1.f / D_) + 1e-5f);
    for (int j = tid; j < D_; j += 256) {
        float r = (v[j] - mu) * rstd * g[j] + be[j];
        out[(size_t)t * D_ + j] = r;
        if (DUAL) out_r[(size_t)t * D_ + j] = f2tf_f(r);
    }
}
__global__ __launch_bounds__(256) void k_ln1(const float* __restrict__ x,
                                             const float* __restrict__ g, const float* __restrict__ be) {
    ln_body<true>(x, d_tmp, g, be, d_x1, d_x1r);
}
__global__ __launch_bounds__(256) void k_ln2(const float* __restrict__ g, const float* __restrict__ be,
                                             float* __restrict__ out) {
    ln_body<false>(d_x1, d_moe, g, be, out, nullptr);
}

// ---------------- routing (reads RAW d_x1) ----------------
__global__ __launch_bounds__(128) void k_route(const float* __restrict__ gW, const float* __restrict__ gb) {
    const int t = blockIdx.x, tid = threadIdx.x;
    float p[E_];
#pragma unroll
    for (int e = 0; e < E_; e++) p[e] = 0.f;
    for (int d = tid; d < D_; d += 128) {
        float xv = d_x1[(size_t)t * D_ + d];
        const float* w = gW + (size_t)d * E_;
#pragma unroll
        for (int e = 0; e < E_; e++) p[e] += xv * w[e];
    }
    __shared__ float red[128][E_];
#pragma unroll
    for (int e = 0; e < E_; e++) red[tid][e] = p[e];
    __syncthreads();
    for (int o = 64; o > 0; o >>= 1) {
        if (tid < o) {
#pragma unroll
            for (int e = 0; e < E_; e++) red[tid][e] += red[tid + o][e];
        }
        __syncthreads();
    }
    if (tid == 0) {
        float l[E_], m = -1e30f;
#pragma unroll
        for (int e = 0; e < E_; e++) { l[e] = red[0][e] + gb[e]; m = fmaxf(m, l[e]); }
        float s = 0.f;
#pragma unroll
        for (int e = 0; e < E_; e++) { l[e] = expf(l[e] - m); s += l[e]; }
        float inv = 1.f / s;
#pragma unroll
        for (int e = 0; e < E_; e++) { l[e] *= inv; d_gsc[t * E_ + e] = l[e]; }
        int i1 = 0;
#pragma unroll
        for (int e = 1; e < E_; e++) if (l[e] > l[i1]) i1 = e;
        int i2 = -1;
#pragma unroll
        for (int e = 0; e < E_; e++) if (e != i1 && (i2 < 0 || l[e] > l[i2])) i2 = e;
        float tot = l[i1] + l[i2];
        d_tok_e[t * 2 + 0] = i1; d_tok_e[t * 2 + 1] = i2;
        d_tok_w[t * 2 + 0] = l[i1] / tot; d_tok_w[t * 2 + 1] = l[i2] / tot;
        atomicAdd(&d_cnt[i1], 1); atomicAdd(&d_cnt[i2], 1);
    }
}

__global__ __launch_bounds__(256) void k_aux(float* __restrict__ aux_out) {
    __shared__ double red[256];
    __shared__ double rw[E_];
    const int tid = threadIdx.x;
    for (int e = 0; e < E_; e++) {
        double s = 0.0;
        for (int t = tid; t < T_; t += 256) s += (double)d_gsc[t * E_ + e];
        red[tid] = s; __syncthreads();
        for (int o = 128; o > 0; o >>= 1) { if (tid < o) red[tid] += red[tid + o]; __syncthreads(); }
        if (tid == 0) rw[e] = red[0] / (double)T_;
        __syncthreads();
    }
    if (tid == 0) {
        double aux = 0.0; int b = 0;
        for (int e = 0; e < E_; e++) {
            aux += ((double)d_cnt[e] / (double)(T_ * 2)) * rw[e];
            d_base[e] = b; b += d_cnt[e];
        }
        *aux_out = (float)((double)E_ * aux);
    }
}

__global__ void k_fill() {
    const int t = blockIdx.x * 256 + threadIdx.x;
    if (t >= T_) return;
    for (int k = 0; k < 2; k++) {
        int e = d_tok_e[t * 2 + k];
        int slot = atomicAdd(&d_fill[e], 1);
        d_list[d_base[e] + slot] = t;
        d_wl[d_base[e] + slot] = d_tok_w[t * 2 + k];
    }
}

// ---------------- launch ----------------
extern "C" void kernel_launch(void* const* d_in, const int* in_sizes, int n_in,
                              void* d_out, int out_size) {
    const float* x     = (const float*)d_in[0];
    const float* Wq    = (const float*)d_in[1];
    const float* bq    = (const float*)d_in[2];
    const float* Wk    = (const float*)d_in[3];
    const float* bk    = (const float*)d_in[4];
    const float* Wv    = (const float*)d_in[5];
    const float* bv    = (const float*)d_in[6];
    const float* Wo    = (const float*)d_in[7];
    const float* bo    = (const float*)d_in[8];
    const float* g1    = (const float*)d_in[9];
    const float* beta1 = (const float*)d_in[10];
    const float* gateW = (const float*)d_in[11];
    const float* gateb = (const float*)d_in[12];
    const float* eW1   = (const float*)d_in[13];
    const float* eb1   = (const float*)d_in[14];
    const float* eW2   = (const float*)d_in[15];
    const float* eb2   = (const float*)d_in[16];
    const float* g2    = (const float*)d_in[17];
    const float* beta2 = (const float*)d_in[18];
    float* out = (float*)d_out;

    const int flash_smem = (64 * LDK + 128 * LDV) * 4;  // 71680 B
    static int attr_set = 0;
    if (!attr_set) {
        cudaFuncSetAttribute(k_flash, cudaFuncAttributeMaxDynamicSharedMemorySize, flash_smem);
        cudaFuncSetAttribute(k_qkv,   cudaFuncAttributeMaxDynamicSharedMemorySize, GEMM_SMEM);
        cudaFuncSetAttribute(k_oproj, cudaFuncAttributeMaxDynamicSharedMemorySize, GEMM_SMEM);
        cudaFuncSetAttribute(k_moe1,  cudaFuncAttributeMaxDynamicSharedMemorySize, GEMM_SMEM);
        cudaFuncSetAttribute(k_moe2,  cudaFuncAttributeMaxDynamicSharedMemorySize, GEMM_SMEM);
        attr_set = 1;
    }

    float *wq_t, *wk_t, *wv_t, *wo_t, *ew1_t, *ew2_t, *xt;
    cudaGetSymbolAddress((void**)&wq_t, d_wq_t);
    cudaGetSymbolAddress((void**)&wk_t, d_wk_t);
    cudaGetSymbolAddress((void**)&wv_t, d_wv_t);
    cudaGetSymbolAddress((void**)&wo_t, d_wo_t);
    cudaGetSymbolAddress((void**)&ew1_t, d_ew1_t);
    cudaGetSymbolAddress((void**)&ew2_t, d_ew2_t);
    cudaGetSymbolAddress((void**)&xt, d_xt);

    const int n4_dd = D_ * D_ / 4, n4_e = E_ * D_ * F_ / 4, n4_x = T_ * D_ / 4;
    k_cvt<<<(n4_dd + 255) / 256, 256>>>(Wq, wq_t, n4_dd);
    k_cvt<<<(n4_dd + 255) / 256, 256>>>(Wk, wk_t, n4_dd);
    k_cvt<<<(n4_dd + 255) / 256, 256>>>(Wv, wv_t, n4_dd);
    k_cvt<<<(n4_dd + 255) / 256, 256>>>(Wo, wo_t, n4_dd);
    k_cvt<<<(n4_e + 255) / 256, 256>>>(eW1, ew1_t, n4_e);
    k_cvt<<<(n4_e + 255) / 256, 256>>>(eW2, ew2_t, n4_e);
    k_cvt<<<(n4_x + 255) / 256, 256>>>(x, xt, n4_x);

    k_zero<<<(T_ * D_) / 256, 256>>>();
    k_qkv<<<dim3(D_ / 128, T_ / 128, 3), 256, GEMM_SMEM>>>(bq, bk, bv);
    k_flash<<<dim3(S_ / 128, BH_), 256, flash_smem>>>();
    k_oproj<<<dim3(D_ / 128, T_ / 128), 256, GEMM_SMEM>>>(bo);
    k_ln1<<<T_, 256>>>(x, g1, beta1);
    k_route<<<T_, 128>>>(gateW, gateb);
    k_aux<<<1, 256>>>(out + (out_size - 1));
    k_fill<<<T_ / 256, 256>>>();
    k_moe1<<<dim3(F_ / 128, T_ / 128, E_), 256, GEMM_SMEM>>>(eb1);
    k_moe2<<<dim3(D_ / 128, T_ / 128, E_), 256, GEMM_SMEM>>>(eb2);
    k_ln2<<<T_, 256>>>(g2, beta2, out);
}